// round 6
// baseline (speedup 1.0000x reference)
#include <cuda_runtime.h>
#include <cstdint>

#define NNODES 100000
#define NEDGES 1600000
#define IN_C 64
#define HID 128
#define OUT_C 64
#define NBT 128            // nodes per MLP tile
#define NTILES ((NNODES + NBT - 1) / NBT)   // 782 (781 full + 32-node tail)
#define XT_STR 132         // padded strides (bank-conflict avoidance)
#define HT_STR 132
#define SCAN_BLK 1024
#define SCAN_NB ((NNODES + SCAN_BLK - 1) / SCAN_BLK)   // 98 blocks, co-resident

// Scratch (static device arrays; heap alloc is forbidden)
__device__ __align__(16) float g_h2[(size_t)NNODES * OUT_C]; // unscaled h2, 25.6 MB
__device__ float g_dinv[NNODES];
__device__ int   g_degi[NNODES];     // in-degree (edges only); memset to 0 per call
__device__ int   g_off[NNODES];      // CSR offsets; scatter bumps them to 'end'
__device__ int   g_esrc[NEDGES];     // CSR: src node per slot, grouped by dst
__device__ unsigned long long g_scanstate[SCAN_NB];  // lookback states; memset per call

// ---------------------------------------------------------------------------
// Per-block index-width detection: int64 ids < 2^31 have zero high words at
// int32 view positions 1,3,...,63. Genuine int32 ids are uniform in [0,1e5).
// ---------------------------------------------------------------------------
__device__ __forceinline__ int detect_stride(const int* __restrict__ ei, int* s_st) {
    if (threadIdx.x < 32) {
        int z = (ei[2 * threadIdx.x + 1] == 0);
        unsigned m = __ballot_sync(0xFFFFFFFFu, z);
        if (threadIdx.x == 0) *s_st = (m == 0xFFFFFFFFu) ? 2 : 1;
    }
    __syncthreads();
    return *s_st;
}

__global__ __launch_bounds__(256) void k_deg_count(const int* __restrict__ ei) {
    __shared__ int s_st;
    const int st = detect_stride(ei, &s_st);
    int e = blockIdx.x * blockDim.x + threadIdx.x;
    if (e < NEDGES) {
        int d = ei[(size_t)NEDGES * st + (size_t)e * st];
        if ((unsigned)d < NNODES) atomicAdd(&g_degi[d], 1);
    }
}

// ---------------------------------------------------------------------------
// Single-pass exclusive scan (decoupled lookback) of g_degi -> g_off; + dinv.
// ---------------------------------------------------------------------------
__global__ __launch_bounds__(SCAN_BLK) void k_scan() {
    __shared__ int wsum[32];
    __shared__ int s_total, s_prefix;
    const int t = threadIdx.x;
    const int bid = blockIdx.x;
    const int i = bid * SCAN_BLK + t;
    const int v = (i < NNODES) ? g_degi[i] : 0;
    if (i < NNODES) g_dinv[i] = rsqrtf((float)(v + 1));   // +1 self-loop

    int x = v;
    #pragma unroll
    for (int o = 1; o < 32; o <<= 1) {
        int y = __shfl_up_sync(0xFFFFFFFFu, x, o);
        if ((t & 31) >= o) x += y;
    }
    if ((t & 31) == 31) wsum[t >> 5] = x;
    __syncthreads();
    if (t < 32) {
        int w = wsum[t];
        int xx = w;
        #pragma unroll
        for (int o = 1; o < 32; o <<= 1) {
            int y = __shfl_up_sync(0xFFFFFFFFu, xx, o);
            if (t >= o) xx += y;
        }
        wsum[t] = xx - w;
        if (t == 31) s_total = xx;
    }
    __syncthreads();

    if (t == 0) {
        unsigned long long flag = (bid == 0) ? 2ULL : 1ULL;
        __threadfence();
        *(volatile unsigned long long*)&g_scanstate[bid] =
            (flag << 32) | (unsigned)s_total;
        if (bid == 0) s_prefix = 0;
    }

    if (bid > 0 && t < 32) {
        int running = 0;
        int base = bid - 1;
        for (;;) {
            int j = base - t;
            unsigned long long s;
            if (j >= 0) {
                do { s = *(volatile unsigned long long*)&g_scanstate[j]; }
                while ((s >> 32) == 0);
            } else {
                s = (2ULL << 32);
            }
            int flag = (int)(s >> 32);
            int val  = (int)(s & 0xFFFFFFFFu);
            unsigned pmask = __ballot_sync(0xFFFFFFFFu, flag == 2);
            if (pmask) {
                int stop = __ffs(pmask) - 1;
                int contrib = (t <= stop) ? val : 0;
                #pragma unroll
                for (int o = 16; o >= 1; o >>= 1)
                    contrib += __shfl_down_sync(0xFFFFFFFFu, contrib, o);
                running += __shfl_sync(0xFFFFFFFFu, contrib, 0);
                break;
            } else {
                int contrib = val;
                #pragma unroll
                for (int o = 16; o >= 1; o >>= 1)
                    contrib += __shfl_down_sync(0xFFFFFFFFu, contrib, o);
                running += __shfl_sync(0xFFFFFFFFu, contrib, 0);
                base -= 32;
            }
        }
        if (t == 0) {
            __threadfence();
            *(volatile unsigned long long*)&g_scanstate[bid] =
                (2ULL << 32) | (unsigned)(running + s_total);
            s_prefix = running;
        }
    }
    __syncthreads();

    if (i < NNODES) g_off[i] = (x - v + wsum[t >> 5]) + s_prefix;
}

__global__ __launch_bounds__(256) void k_scatter(const int* __restrict__ ei) {
    __shared__ int s_st;
    const int st = detect_stride(ei, &s_st);
    int e = blockIdx.x * blockDim.x + threadIdx.x;
    if (e < NEDGES) {
        int s = ei[(size_t)e * st];
        int d = ei[(size_t)NEDGES * st + (size_t)e * st];
        if ((unsigned)s < NNODES && (unsigned)d < NNODES) {
            int pos = atomicAdd(&g_off[d], 1);
            g_esrc[pos] = s;
        }
    }
}

// ---------------------------------------------------------------------------
// Fused MLP, register-tiled: g_h2[n] = relu(X@W1+b1)[n] @ W2
// Tile = 128 nodes. Transposed smem operands so both GEMM operands are
// float4 along the lane dimension. Phase1: 8x8 reg tile; Phase2: 4x8.
// ---------------------------------------------------------------------------
__global__ __launch_bounds__(256, 1) void k_mlp(
    const float* __restrict__ X, const float* __restrict__ W1,
    const float* __restrict__ b1, const float* __restrict__ W2)
{
    extern __shared__ float sm[];
    float* sW1 = sm;                    // 64*128 = 8192 floats [k][col]
    float* sW2 = sW1 + IN_C * HID;      // 128*64 = 8192 [k][col]
    float* sb1 = sW2 + HID * OUT_C;     // 128
    float* sXT = sb1 + HID;             // 64 x XT_STR  [k][node]
    float* sHT = sXT + IN_C * XT_STR;   // 128 x HT_STR [k][node]

    const int t = threadIdx.x;

    for (int i = t; i < IN_C * HID / 4; i += 256)
        ((float4*)sW1)[i] = ((const float4*)W1)[i];
    for (int i = t; i < HID * OUT_C / 4; i += 256)
        ((float4*)sW2)[i] = ((const float4*)W2)[i];
    if (t < HID) sb1[t] = b1[t];

    const int tc  = t & 15;            // phase1 col-octet (16 x 8 = 128 cols)
    const int tn  = t >> 4;            // phase1 node-octet (16 x 8 = 128 nodes)
    // phase2: tc = col-quad (16 x 4 = 64 cols), tn = node-octet (same split)
    const int sn  = t & 127;           // staging: node
    const int skh = t >> 7;            // staging: k half (0..1)

    for (int tile = blockIdx.x; tile < NTILES; tile += gridDim.x) {
        const int base = tile * NBT;

        // ---- stage X^T (conflict-free: bank = const + node) ----
        {
            const int gn = base + sn;
            if (gn < NNODES) {
                const float4* xr = (const float4*)(X + (size_t)gn * IN_C + skh * 32);
                #pragma unroll
                for (int f = 0; f < 8; f++) {
                    float4 v = xr[f];
                    int k = skh * 32 + f * 4;
                    sXT[(k + 0) * XT_STR + sn] = v.x;
                    sXT[(k + 1) * XT_STR + sn] = v.y;
                    sXT[(k + 2) * XT_STR + sn] = v.z;
                    sXT[(k + 3) * XT_STR + sn] = v.w;
                }
            } else {
                #pragma unroll
                for (int f = 0; f < 8; f++) {
                    int k = skh * 32 + f * 4;
                    sXT[(k + 0) * XT_STR + sn] = 0.f;
                    sXT[(k + 1) * XT_STR + sn] = 0.f;
                    sXT[(k + 2) * XT_STR + sn] = 0.f;
                    sXT[(k + 3) * XT_STR + sn] = 0.f;
                }
            }
        }
        __syncthreads();

        // ---- Phase 1: sHT[col][node] = relu(X@W1+b1), 8 cols x 8 nodes ----
        {
            float acc[8][8];   // [c][n]
            float4 bA = ((const float4*)sb1)[tc * 2];
            float4 bB = ((const float4*)sb1)[tc * 2 + 1];
            float bs[8] = {bA.x, bA.y, bA.z, bA.w, bB.x, bB.y, bB.z, bB.w};
            #pragma unroll
            for (int c = 0; c < 8; c++)
                #pragma unroll
                for (int n = 0; n < 8; n++) acc[c][n] = bs[c];

            #pragma unroll 4
            for (int k = 0; k < IN_C; k++) {
                float4 w0 = *(const float4*)&sW1[k * HID + tc * 8];
                float4 w1 = *(const float4*)&sW1[k * HID + tc * 8 + 4];
                float4 x0 = *(const float4*)&sXT[k * XT_STR + tn * 8];
                float4 x1 = *(const float4*)&sXT[k * XT_STR + tn * 8 + 4];
                float wv[8] = {w0.x, w0.y, w0.z, w0.w, w1.x, w1.y, w1.z, w1.w};
                float xv[8] = {x0.x, x0.y, x0.z, x0.w, x1.x, x1.y, x1.z, x1.w};
                #pragma unroll
                for (int c = 0; c < 8; c++)
                    #pragma unroll
                    for (int n = 0; n < 8; n++)
                        acc[c][n] = fmaf(wv[c], xv[n], acc[c][n]);
            }

            // relu + transposed store, column order staggered by tc
            #pragma unroll
            for (int cc = 0; cc < 8; cc++) {
                int c = (cc + tc) & 7;
                int col = tc * 8 + c;
                float4 s0 = make_float4(fmaxf(acc[c][0], 0.f), fmaxf(acc[c][1], 0.f),
                                        fmaxf(acc[c][2], 0.f), fmaxf(acc[c][3], 0.f));
                float4 s1 = make_float4(fmaxf(acc[c][4], 0.f), fmaxf(acc[c][5], 0.f),
                                        fmaxf(acc[c][6], 0.f), fmaxf(acc[c][7], 0.f));
                *(float4*)&sHT[col * HT_STR + tn * 8]     = s0;
                *(float4*)&sHT[col * HT_STR + tn * 8 + 4] = s1;
            }
        }
        __syncthreads();

        // ---- Phase 2: g_h2 = H @ W2, 4 cols x 8 nodes per thread ----
        {
            float a2[4][8];
            #pragma unroll
            for (int c = 0; c < 4; c++)
                #pragma unroll
                for (int n = 0; n < 8; n++) a2[c][n] = 0.f;

            #pragma unroll 4
            for (int k = 0; k < HID; k++) {
                float4 w  = *(const float4*)&sW2[k * OUT_C + tc * 4];
                float4 x0 = *(const float4*)&sHT[k * HT_STR + tn * 8];
                float4 x1 = *(const float4*)&sHT[k * HT_STR + tn * 8 + 4];
                float wv[4] = {w.x, w.y, w.z, w.w};
                float xv[8] = {x0.x, x0.y, x0.z, x0.w, x1.x, x1.y, x1.z, x1.w};
                #pragma unroll
                for (int c = 0; c < 4; c++)
                    #pragma unroll
                    for (int n = 0; n < 8; n++)
                        a2[c][n] = fmaf(wv[c], xv[n], a2[c][n]);
            }

            #pragma unroll
            for (int n = 0; n < 8; n++) {
                int gn = base + tn * 8 + n;
                if (gn < NNODES) {
                    float4 o = make_float4(a2[0][n], a2[1][n], a2[2][n], a2[3][n]);
                    *(float4*)&g_h2[(size_t)gn * OUT_C + tc * 4] = o;
                }
            }
        }
        __syncthreads();   // sHT/sXT reuse next tile
    }
}

// ---------------------------------------------------------------------------
// Pull aggregation: one warp per dst node, lane owns a float2 column chunk.
//   out[n] = dinv[n] * ( dinv[n]*h2[n] + sum_{s->n} dinv[s]*h2[s] ) + b2
// ---------------------------------------------------------------------------
__global__ __launch_bounds__(256) void k_pull(
    const float* __restrict__ b2, float* __restrict__ out)
{
    const int warp = (blockIdx.x * blockDim.x + threadIdx.x) >> 5;
    const int lane = threadIdx.x & 31;
    if (warp >= NNODES) return;
    const int n = warp;

    const float2* __restrict__ tab = (const float2*)g_h2;
    const float din = g_dinv[n];

    float2 self = tab[(size_t)n * (OUT_C / 2) + lane];
    float2 acc;
    acc.x = din * self.x;
    acc.y = din * self.y;

    const int deg = g_degi[n];
    const int end = g_off[n];           // scatter bumped off to 'end'
    const int beg = end - deg;

    int i = beg;
    for (; i + 1 < end; i += 2) {
        const int s0 = __ldg(&g_esrc[i]);
        const int s1 = __ldg(&g_esrc[i + 1]);
        const float d0 = g_dinv[s0];
        const float d1 = g_dinv[s1];
        float2 v0 = tab[(size_t)s0 * (OUT_C / 2) + lane];
        float2 v1 = tab[(size_t)s1 * (OUT_C / 2) + lane];
        acc.x = fmaf(d0, v0.x, acc.x);
        acc.y = fmaf(d0, v0.y, acc.y);
        acc.x = fmaf(d1, v1.x, acc.x);
        acc.y = fmaf(d1, v1.y, acc.y);
    }
    if (i < end) {
        const int s = __ldg(&g_esrc[i]);
        const float ds = g_dinv[s];
        float2 v = tab[(size_t)s * (OUT_C / 2) + lane];
        acc.x = fmaf(ds, v.x, acc.x);
        acc.y = fmaf(ds, v.y, acc.y);
    }

    const float2 bb = ((const float2*)b2)[lane];
    float2 o;
    o.x = fmaf(din, acc.x, bb.x);
    o.y = fmaf(din, acc.y, bb.y);
    ((float2*)out)[(size_t)n * (OUT_C / 2) + lane] = o;
}

// ---------------------------------------------------------------------------
extern "C" void kernel_launch(void* const* d_in, const int* in_sizes, int n_in,
                              void* d_out, int out_size)
{
    const float* X   = (const float*)d_in[0];
    const int*   ei  = (const int*)d_in[1];   // width auto-detected per block
    const float* W1  = (const float*)d_in[2];
    const float* b1  = (const float*)d_in[3];
    const float* W2  = (const float*)d_in[4];
    const float* b2  = (const float*)d_in[5];
    float*       out = (float*)d_out;

    const int smem_bytes =
        (IN_C*HID + HID*OUT_C + HID + IN_C*XT_STR + HID*HT_STR) * 4;  // ~164 KB

    static cudaStream_t s1;
    static cudaEvent_t evRoot, evMlp;
    static void *p_degi, *p_state;
    static int init_done = 0;
    if (!init_done) {
        cudaFuncSetAttribute(k_mlp, cudaFuncAttributeMaxDynamicSharedMemorySize, smem_bytes);
        cudaStreamCreateWithFlags(&s1, cudaStreamNonBlocking);
        cudaEventCreateWithFlags(&evRoot, cudaEventDisableTiming);
        cudaEventCreateWithFlags(&evMlp, cudaEventDisableTiming);
        cudaGetSymbolAddress(&p_degi, g_degi);
        cudaGetSymbolAddress(&p_state, g_scanstate);
        init_done = 1;
    }

    cudaEventRecord(evRoot, 0);

    // Critical chain on the capture (legacy) stream.
    cudaMemsetAsync(p_degi, 0, NNODES * sizeof(int), 0);
    cudaMemsetAsync(p_state, 0, SCAN_NB * sizeof(unsigned long long), 0);
    k_deg_count<<<(NEDGES + 255) / 256, 256>>>(ei);
    k_scan     <<<SCAN_NB, SCAN_BLK>>>();
    k_scatter  <<<(NEDGES + 255) / 256, 256>>>(ei);

    // Fork: MLP depends only on the root.
    cudaStreamWaitEvent(s1, evRoot, 0);
    k_mlp<<<148, 256, smem_bytes, s1>>>(X, W1, b1, W2);
    cudaEventRecord(evMlp, s1);

    // Join, then pull.
    cudaStreamWaitEvent(0, evMlp, 0);
    k_pull     <<<(NNODES * 32 + 255) / 256, 256>>>(b2, out);
}

// round 8
// speedup vs baseline: 1.5523x; 1.5523x over previous
#include <cuda_runtime.h>
#include <cstdint>

#define NNODES 100000
#define NEDGES 1600000
#define IN_C 64
#define HID 128
#define OUT_C 64
#define NBT 128            // nodes per MLP tile
#define NTILES ((NNODES + NBT - 1) / NBT)   // 782 (781 full + 32-node tail)
#define XT_STR 132
#define HT_STR 132
#define SCAN_BLK 1024
#define SCAN_NB ((NNODES + SCAN_BLK - 1) / SCAN_BLK)   // 98 blocks, co-resident

// Scratch (static device arrays; heap alloc is forbidden)
__device__ __align__(16) float g_h2[(size_t)NNODES * OUT_C]; // unscaled h2, 25.6 MB
__device__ float g_dinv[NNODES];
__device__ int   g_degi[NNODES];
__device__ int   g_off[NNODES];      // CSR offsets; scatter bumps them to 'end'
__device__ int   g_esrc[NEDGES];
__device__ unsigned long long g_scanstate[SCAN_NB];

// ---------------------------------------------------------------------------
__device__ __forceinline__ int detect_stride(const int* __restrict__ ei, int* s_st) {
    if (threadIdx.x < 32) {
        int z = (ei[2 * threadIdx.x + 1] == 0);
        unsigned m = __ballot_sync(0xFFFFFFFFu, z);
        if (threadIdx.x == 0) *s_st = (m == 0xFFFFFFFFu) ? 2 : 1;
    }
    __syncthreads();
    return *s_st;
}

__global__ __launch_bounds__(256) void k_deg_count(const int* __restrict__ ei) {
    __shared__ int s_st;
    const int st = detect_stride(ei, &s_st);
    int e = blockIdx.x * blockDim.x + threadIdx.x;
    if (e < NEDGES) {
        int d = ei[(size_t)NEDGES * st + (size_t)e * st];
        if ((unsigned)d < NNODES) atomicAdd(&g_degi[d], 1);
    }
}

// ---------------------------------------------------------------------------
// Single-pass exclusive scan (decoupled lookback) of g_degi -> g_off; + dinv.
// ---------------------------------------------------------------------------
__global__ __launch_bounds__(SCAN_BLK) void k_scan() {
    __shared__ int wsum[32];
    __shared__ int s_total, s_prefix;
    const int t = threadIdx.x;
    const int bid = blockIdx.x;
    const int i = bid * SCAN_BLK + t;
    const int v = (i < NNODES) ? g_degi[i] : 0;
    if (i < NNODES) g_dinv[i] = rsqrtf((float)(v + 1));

    int x = v;
    #pragma unroll
    for (int o = 1; o < 32; o <<= 1) {
        int y = __shfl_up_sync(0xFFFFFFFFu, x, o);
        if ((t & 31) >= o) x += y;
    }
    if ((t & 31) == 31) wsum[t >> 5] = x;
    __syncthreads();
    if (t < 32) {
        int w = wsum[t];
        int xx = w;
        #pragma unroll
        for (int o = 1; o < 32; o <<= 1) {
            int y = __shfl_up_sync(0xFFFFFFFFu, xx, o);
            if (t >= o) xx += y;
        }
        wsum[t] = xx - w;
        if (t == 31) s_total = xx;
    }
    __syncthreads();

    if (t == 0) {
        unsigned long long flag = (bid == 0) ? 2ULL : 1ULL;
        __threadfence();
        *(volatile unsigned long long*)&g_scanstate[bid] =
            (flag << 32) | (unsigned)s_total;
        if (bid == 0) s_prefix = 0;
    }

    if (bid > 0 && t < 32) {
        int running = 0;
        int base = bid - 1;
        for (;;) {
            int j = base - t;
            unsigned long long s;
            if (j >= 0) {
                do { s = *(volatile unsigned long long*)&g_scanstate[j]; }
                while ((s >> 32) == 0);
            } else {
                s = (2ULL << 32);
            }
            int flag = (int)(s >> 32);
            int val  = (int)(s & 0xFFFFFFFFu);
            unsigned pmask = __ballot_sync(0xFFFFFFFFu, flag == 2);
            if (pmask) {
                int stop = __ffs(pmask) - 1;
                int contrib = (t <= stop) ? val : 0;
                #pragma unroll
                for (int o = 16; o >= 1; o >>= 1)
                    contrib += __shfl_down_sync(0xFFFFFFFFu, contrib, o);
                running += __shfl_sync(0xFFFFFFFFu, contrib, 0);
                break;
            } else {
                int contrib = val;
                #pragma unroll
                for (int o = 16; o >= 1; o >>= 1)
                    contrib += __shfl_down_sync(0xFFFFFFFFu, contrib, o);
                running += __shfl_sync(0xFFFFFFFFu, contrib, 0);
                base -= 32;
            }
        }
        if (t == 0) {
            __threadfence();
            *(volatile unsigned long long*)&g_scanstate[bid] =
                (2ULL << 32) | (unsigned)(running + s_total);
            s_prefix = running;
        }
    }
    __syncthreads();

    if (i < NNODES) g_off[i] = (x - v + wsum[t >> 5]) + s_prefix;
}

__global__ __launch_bounds__(256) void k_scatter(const int* __restrict__ ei) {
    __shared__ int s_st;
    const int st = detect_stride(ei, &s_st);
    int e = blockIdx.x * blockDim.x + threadIdx.x;
    if (e < NEDGES) {
        int s = ei[(size_t)e * st];
        int d = ei[(size_t)NEDGES * st + (size_t)e * st];
        if ((unsigned)s < NNODES && (unsigned)d < NNODES) {
            int pos = atomicAdd(&g_off[d], 1);
            g_esrc[pos] = s;
        }
    }
}

// ---------------------------------------------------------------------------
// Fused MLP, register-tiled, NO runtime array indices anywhere.
//   g_h2[n] = relu(X@W1+b1)[n] @ W2
// sHT rows are stored under the bijection phi(col) = (col&3)*32 + (col>>2);
// sW2s is staged pre-permuted by the same phi, so phase 2 iterates raw rows.
// ---------------------------------------------------------------------------
__global__ __launch_bounds__(256, 1) void k_mlp(
    const float* __restrict__ X, const float* __restrict__ W1,
    const float* __restrict__ b1, const float* __restrict__ W2)
{
    extern __shared__ float sm[];
    float* sW1  = sm;                    // 64*128 [k][col]
    float* sW2s = sW1 + IN_C * HID;      // 128*64 [phi(k)][col]
    float* sb1  = sW2s + HID * OUT_C;    // 128
    float* sXT  = sb1 + HID;             // 64 x XT_STR  [k][node]
    float* sHT  = sXT + IN_C * XT_STR;   // 128 x HT_STR [phi(col)][node]

    const int t = threadIdx.x;

    for (int i = t; i < IN_C * HID / 4; i += 256)
        ((float4*)sW1)[i] = ((const float4*)W1)[i];
    // stage W2 with phi-permuted rows
    for (int i = t; i < HID * OUT_C / 4; i += 256) {
        int k = i >> 4, cq = i & 15;
        int r = (k & 3) * 32 + (k >> 2);          // phi(k)
        ((float4*)sW2s)[r * 16 + cq] = ((const float4*)W2)[i];
    }
    if (t < HID) sb1[t] = b1[t];

    const int c4a = t & 31;            // phase1: col quad (32 x 4 = 128 cols)
    const int no  = t >> 5;            // phase1: node group of 16 (8 x 16 = 128)
    const int cq  = t & 15;            // phase2: col quad (16 x 4 = 64 cols)
    const int ng  = t >> 4;            // phase2: node group of 8 (16 x 8 = 128)
    const int sn  = t & 127;           // staging: node
    const int skh = t >> 7;            // staging: k half

    for (int tile = blockIdx.x; tile < NTILES; tile += gridDim.x) {
        const int base = tile * NBT;

        // ---- stage X^T [k][node] (conflict-free scalar stores) ----
        {
            const int gn = base + sn;
            if (gn < NNODES) {
                const float4* xr = (const float4*)(X + (size_t)gn * IN_C + skh * 32);
                #pragma unroll
                for (int f = 0; f < 8; f++) {
                    float4 v = xr[f];
                    int k = skh * 32 + f * 4;
                    sXT[(k + 0) * XT_STR + sn] = v.x;
                    sXT[(k + 1) * XT_STR + sn] = v.y;
                    sXT[(k + 2) * XT_STR + sn] = v.z;
                    sXT[(k + 3) * XT_STR + sn] = v.w;
                }
            } else {
                #pragma unroll
                for (int f = 0; f < 8; f++) {
                    int k = skh * 32 + f * 4;
                    sXT[(k + 0) * XT_STR + sn] = 0.f;
                    sXT[(k + 1) * XT_STR + sn] = 0.f;
                    sXT[(k + 2) * XT_STR + sn] = 0.f;
                    sXT[(k + 3) * XT_STR + sn] = 0.f;
                }
            }
        }
        __syncthreads();

        // ---- Phase 1: 4 cols x 16 nodes per thread ----
        {
            float4 bias = ((const float4*)sb1)[c4a];
            float acc0[16], acc1[16], acc2[16], acc3[16];
            #pragma unroll
            for (int n = 0; n < 16; n++) {
                acc0[n] = bias.x; acc1[n] = bias.y;
                acc2[n] = bias.z; acc3[n] = bias.w;
            }

            #pragma unroll 4
            for (int k = 0; k < IN_C; k++) {
                float4 w  = *(const float4*)&sW1[k * HID + c4a * 4];
                const float* xr = &sXT[k * XT_STR + no * 16];
                float4 x0 = *(const float4*)(xr);
                float4 x1 = *(const float4*)(xr + 4);
                float4 x2 = *(const float4*)(xr + 8);
                float4 x3 = *(const float4*)(xr + 12);
                float xv[16] = {x0.x,x0.y,x0.z,x0.w, x1.x,x1.y,x1.z,x1.w,
                                x2.x,x2.y,x2.z,x2.w, x3.x,x3.y,x3.z,x3.w};
                #pragma unroll
                for (int n = 0; n < 16; n++) {
                    acc0[n] = fmaf(w.x, xv[n], acc0[n]);
                    acc1[n] = fmaf(w.y, xv[n], acc1[n]);
                    acc2[n] = fmaf(w.z, xv[n], acc2[n]);
                    acc3[n] = fmaf(w.w, xv[n], acc3[n]);
                }
            }

            // relu + store: row = phi(col) = c*32 + c4a  (compile-time c)
            #pragma unroll
            for (int m = 0; m < 4; m++) {
                float* d0 = &sHT[(0 * 32 + c4a) * HT_STR + no * 16 + m * 4];
                float* d1 = &sHT[(1 * 32 + c4a) * HT_STR + no * 16 + m * 4];
                float* d2 = &sHT[(2 * 32 + c4a) * HT_STR + no * 16 + m * 4];
                float* d3 = &sHT[(3 * 32 + c4a) * HT_STR + no * 16 + m * 4];
                *(float4*)d0 = make_float4(fmaxf(acc0[m*4+0],0.f), fmaxf(acc0[m*4+1],0.f),
                                           fmaxf(acc0[m*4+2],0.f), fmaxf(acc0[m*4+3],0.f));
                *(float4*)d1 = make_float4(fmaxf(acc1[m*4+0],0.f), fmaxf(acc1[m*4+1],0.f),
                                           fmaxf(acc1[m*4+2],0.f), fmaxf(acc1[m*4+3],0.f));
                *(float4*)d2 = make_float4(fmaxf(acc2[m*4+0],0.f), fmaxf(acc2[m*4+1],0.f),
                                           fmaxf(acc2[m*4+2],0.f), fmaxf(acc2[m*4+3],0.f));
                *(float4*)d3 = make_float4(fmaxf(acc3[m*4+0],0.f), fmaxf(acc3[m*4+1],0.f),
                                           fmaxf(acc3[m*4+2],0.f), fmaxf(acc3[m*4+3],0.f));
            }
        }
        __syncthreads();

        // ---- Phase 2: 4 cols x 8 nodes per thread, iterate phys rows ----
        {
            float a0[8], a1[8], a2r[8], a3[8];
            #pragma unroll
            for (int n = 0; n < 8; n++) { a0[n]=0.f; a1[n]=0.f; a2r[n]=0.f; a3[n]=0.f; }

            #pragma unroll 4
            for (int r = 0; r < HID; r++) {
                float4 w  = *(const float4*)&sW2s[r * OUT_C + cq * 4];
                const float* xr = &sHT[r * HT_STR + ng * 8];
                float4 x0 = *(const float4*)(xr);
                float4 x1 = *(const float4*)(xr + 4);
                float xv[8] = {x0.x,x0.y,x0.z,x0.w, x1.x,x1.y,x1.z,x1.w};
                #pragma unroll
                for (int n = 0; n < 8; n++) {
                    a0[n]  = fmaf(w.x, xv[n], a0[n]);
                    a1[n]  = fmaf(w.y, xv[n], a1[n]);
                    a2r[n] = fmaf(w.z, xv[n], a2r[n]);
                    a3[n]  = fmaf(w.w, xv[n], a3[n]);
                }
            }

            #pragma unroll
            for (int n = 0; n < 8; n++) {
                int gn = base + ng * 8 + n;
                if (gn < NNODES) {
                    *(float4*)&g_h2[(size_t)gn * OUT_C + cq * 4] =
                        make_float4(a0[n], a1[n], a2r[n], a3[n]);
                }
            }
        }
        __syncthreads();
    }
}

// ---------------------------------------------------------------------------
// Pull aggregation: one warp per dst node, lane owns a float2 column chunk.
// ---------------------------------------------------------------------------
__global__ __launch_bounds__(256) void k_pull(
    const float* __restrict__ b2, float* __restrict__ out)
{
    const int warp = (blockIdx.x * blockDim.x + threadIdx.x) >> 5;
    const int lane = threadIdx.x & 31;
    if (warp >= NNODES) return;
    const int n = warp;

    const float2* __restrict__ tab = (const float2*)g_h2;
    const float din = g_dinv[n];

    float2 self = tab[(size_t)n * (OUT_C / 2) + lane];
    float2 acc;
    acc.x = din * self.x;
    acc.y = din * self.y;

    const int deg = g_degi[n];
    const int end = g_off[n];
    const int beg = end - deg;

    int i = beg;
    for (; i + 1 < end; i += 2) {
        const int s0 = __ldg(&g_esrc[i]);
        const int s1 = __ldg(&g_esrc[i + 1]);
        const float d0 = g_dinv[s0];
        const float d1 = g_dinv[s1];
        float2 v0 = tab[(size_t)s0 * (OUT_C / 2) + lane];
        float2 v1 = tab[(size_t)s1 * (OUT_C / 2) + lane];
        acc.x = fmaf(d0, v0.x, acc.x);
        acc.y = fmaf(d0, v0.y, acc.y);
        acc.x = fmaf(d1, v1.x, acc.x);
        acc.y = fmaf(d1, v1.y, acc.y);
    }
    if (i < end) {
        const int s = __ldg(&g_esrc[i]);
        const float ds = g_dinv[s];
        float2 v = tab[(size_t)s * (OUT_C / 2) + lane];
        acc.x = fmaf(ds, v.x, acc.x);
        acc.y = fmaf(ds, v.y, acc.y);
    }

    const float2 bb = ((const float2*)b2)[lane];
    float2 o;
    o.x = fmaf(din, acc.x, bb.x);
    o.y = fmaf(din, acc.y, bb.y);
    ((float2*)out)[(size_t)n * (OUT_C / 2) + lane] = o;
}

// ---------------------------------------------------------------------------
extern "C" void kernel_launch(void* const* d_in, const int* in_sizes, int n_in,
                              void* d_out, int out_size)
{
    const float* X   = (const float*)d_in[0];
    const int*   ei  = (const int*)d_in[1];
    const float* W1  = (const float*)d_in[2];
    const float* b1  = (const float*)d_in[3];
    const float* W2  = (const float*)d_in[4];
    const float* b2  = (const float*)d_in[5];
    float*       out = (float*)d_out;

    const int smem_bytes =
        (IN_C*HID + HID*OUT_C + HID + IN_C*XT_STR + HID*HT_STR) * 4;  // ~164 KB

    static cudaStream_t s1;
    static cudaEvent_t evRoot, evMlp;
    static void *p_degi, *p_state;
    static int init_done = 0;
    if (!init_done) {
        cudaFuncSetAttribute(k_mlp, cudaFuncAttributeMaxDynamicSharedMemorySize, smem_bytes);
        cudaStreamCreateWithFlags(&s1, cudaStreamNonBlocking);
        cudaEventCreateWithFlags(&evRoot, cudaEventDisableTiming);
        cudaEventCreateWithFlags(&evMlp, cudaEventDisableTiming);
        cudaGetSymbolAddress(&p_degi, g_degi);
        cudaGetSymbolAddress(&p_state, g_scanstate);
        init_done = 1;
    }

    cudaEventRecord(evRoot, 0);

    // Critical chain on the capture (legacy) stream.
    cudaMemsetAsync(p_degi, 0, NNODES * sizeof(int), 0);
    cudaMemsetAsync(p_state, 0, SCAN_NB * sizeof(unsigned long long), 0);
    k_deg_count<<<(NEDGES + 255) / 256, 256>>>(ei);
    k_scan     <<<SCAN_NB, SCAN_BLK>>>();
    k_scatter  <<<(NEDGES + 255) / 256, 256>>>(ei);

    // Fork: MLP depends only on the root.
    cudaStreamWaitEvent(s1, evRoot, 0);
    k_mlp<<<148, 256, smem_bytes, s1>>>(X, W1, b1, W2);
    cudaEventRecord(evMlp, s1);

    // Join, then pull.
    cudaStreamWaitEvent(0, evMlp, 0);
    k_pull     <<<(NNODES * 32 + 255) / 256, 256>>>(b2, out);
}

// round 9
// speedup vs baseline: 1.5990x; 1.0301x over previous
#include <cuda_runtime.h>
#include <cstdint>

#define NNODES 100000
#define NEDGES 1600000
#define IN_C 64
#define HID 128
#define OUT_C 64
#define NBT 128            // nodes per MLP tile
#define NTILES ((NNODES + NBT - 1) / NBT)   // 782
#define XT_STR 132
#define HT_STR 132
#define MLP_THREADS 512
#define SCAN_BLK 1024
#define SCAN_NB ((NNODES + SCAN_BLK - 1) / SCAN_BLK)   // 98 blocks, co-resident

// Scratch (static device arrays; heap alloc is forbidden)
__device__ __align__(16) float g_h2[(size_t)NNODES * OUT_C]; // unscaled h2, 25.6 MB
__device__ float g_dinv[NNODES];
__device__ int   g_degi[NNODES];
__device__ int   g_off[NNODES];      // CSR offsets; scatter bumps them to 'end'
__device__ int   g_esrc[NEDGES];
__device__ unsigned long long g_scanstate[SCAN_NB];

// ---------------------------------------------------------------------------
__device__ __forceinline__ int detect_stride(const int* __restrict__ ei, int* s_st) {
    if (threadIdx.x < 32) {
        int z = (ei[2 * threadIdx.x + 1] == 0);
        unsigned m = __ballot_sync(0xFFFFFFFFu, z);
        if (threadIdx.x == 0) *s_st = (m == 0xFFFFFFFFu) ? 2 : 1;
    }
    __syncthreads();
    return *s_st;
}

__global__ __launch_bounds__(256) void k_deg_count(const int* __restrict__ ei) {
    __shared__ int s_st;
    const int st = detect_stride(ei, &s_st);
    int e = blockIdx.x * blockDim.x + threadIdx.x;
    if (e < NEDGES) {
        int d = ei[(size_t)NEDGES * st + (size_t)e * st];
        if ((unsigned)d < NNODES) atomicAdd(&g_degi[d], 1);
    }
}

// ---------------------------------------------------------------------------
// Single-pass exclusive scan (decoupled lookback) of g_degi -> g_off; + dinv.
// ---------------------------------------------------------------------------
__global__ __launch_bounds__(SCAN_BLK) void k_scan() {
    __shared__ int wsum[32];
    __shared__ int s_total, s_prefix;
    const int t = threadIdx.x;
    const int bid = blockIdx.x;
    const int i = bid * SCAN_BLK + t;
    const int v = (i < NNODES) ? g_degi[i] : 0;
    if (i < NNODES) g_dinv[i] = rsqrtf((float)(v + 1));

    int x = v;
    #pragma unroll
    for (int o = 1; o < 32; o <<= 1) {
        int y = __shfl_up_sync(0xFFFFFFFFu, x, o);
        if ((t & 31) >= o) x += y;
    }
    if ((t & 31) == 31) wsum[t >> 5] = x;
    __syncthreads();
    if (t < 32) {
        int w = wsum[t];
        int xx = w;
        #pragma unroll
        for (int o = 1; o < 32; o <<= 1) {
            int y = __shfl_up_sync(0xFFFFFFFFu, xx, o);
            if (t >= o) xx += y;
        }
        wsum[t] = xx - w;
        if (t == 31) s_total = xx;
    }
    __syncthreads();

    if (t == 0) {
        unsigned long long flag = (bid == 0) ? 2ULL : 1ULL;
        __threadfence();
        *(volatile unsigned long long*)&g_scanstate[bid] =
            (flag << 32) | (unsigned)s_total;
        if (bid == 0) s_prefix = 0;
    }

    if (bid > 0 && t < 32) {
        int running = 0;
        int base = bid - 1;
        for (;;) {
            int j = base - t;
            unsigned long long s;
            if (j >= 0) {
                do { s = *(volatile unsigned long long*)&g_scanstate[j]; }
                while ((s >> 32) == 0);
            } else {
                s = (2ULL << 32);
            }
            int flag = (int)(s >> 32);
            int val  = (int)(s & 0xFFFFFFFFu);
            unsigned pmask = __ballot_sync(0xFFFFFFFFu, flag == 2);
            if (pmask) {
                int stop = __ffs(pmask) - 1;
                int contrib = (t <= stop) ? val : 0;
                #pragma unroll
                for (int o = 16; o >= 1; o >>= 1)
                    contrib += __shfl_down_sync(0xFFFFFFFFu, contrib, o);
                running += __shfl_sync(0xFFFFFFFFu, contrib, 0);
                break;
            } else {
                int contrib = val;
                #pragma unroll
                for (int o = 16; o >= 1; o >>= 1)
                    contrib += __shfl_down_sync(0xFFFFFFFFu, contrib, o);
                running += __shfl_sync(0xFFFFFFFFu, contrib, 0);
                base -= 32;
            }
        }
        if (t == 0) {
            __threadfence();
            *(volatile unsigned long long*)&g_scanstate[bid] =
                (2ULL << 32) | (unsigned)(running + s_total);
            s_prefix = running;
        }
    }
    __syncthreads();

    if (i < NNODES) g_off[i] = (x - v + wsum[t >> 5]) + s_prefix;
}

__global__ __launch_bounds__(256) void k_scatter(const int* __restrict__ ei) {
    __shared__ int s_st;
    const int st = detect_stride(ei, &s_st);
    int e = blockIdx.x * blockDim.x + threadIdx.x;
    if (e < NEDGES) {
        int s = ei[(size_t)e * st];
        int d = ei[(size_t)NEDGES * st + (size_t)e * st];
        if ((unsigned)s < NNODES && (unsigned)d < NNODES) {
            int pos = atomicAdd(&g_off[d], 1);
            g_esrc[pos] = s;
        }
    }
}

// ---------------------------------------------------------------------------
// Fused MLP, register-tiled, 512 threads (16 warps/SM for latency hiding).
//   g_h2[n] = relu(X@W1+b1)[n] @ W2
// sHT rows stored under phi(col) = (col&3)*32 + (col>>2); sW2s pre-permuted.
// All accumulator indices are compile-time (no local-mem demotion).
// ---------------------------------------------------------------------------
__global__ __launch_bounds__(MLP_THREADS, 1) void k_mlp(
    const float* __restrict__ X, const float* __restrict__ W1,
    const float* __restrict__ b1, const float* __restrict__ W2)
{
    extern __shared__ float sm[];
    float* sW1  = sm;                    // 64*128 [k][col]
    float* sW2s = sW1 + IN_C * HID;      // 128*64 [phi(k)][col]
    float* sb1  = sW2s + HID * OUT_C;    // 128
    float* sXT  = sb1 + HID;             // 64 x XT_STR  [k][node]
    float* sHT  = sXT + IN_C * XT_STR;   // 128 x HT_STR [phi(col)][node]

    const int t = threadIdx.x;

    for (int i = t; i < IN_C * HID / 4; i += MLP_THREADS)
        ((float4*)sW1)[i] = ((const float4*)W1)[i];
    for (int i = t; i < HID * OUT_C / 4; i += MLP_THREADS) {
        int k = i >> 4, cq = i & 15;
        int r = (k & 3) * 32 + (k >> 2);          // phi(k)
        ((float4*)sW2s)[r * 16 + cq] = ((const float4*)W2)[i];
    }
    if (t < HID) sb1[t] = b1[t];

    const int c4a = t & 31;            // phase1: col quad (32 x 4 = 128 cols)
    const int no  = t >> 5;            // phase1: node octet (16 x 8 = 128) — warp-uniform
    const int cq  = t & 15;            // phase2: col quad (16 x 4 = 64 cols)
    const int ng  = t >> 4;            // phase2: node quad (32 x 4 = 128)
    const int sn  = t & 127;           // staging: node
    const int skq = t >> 7;            // staging: k quarter (0..3)

    for (int tile = blockIdx.x; tile < NTILES; tile += gridDim.x) {
        const int base = tile * NBT;

        // ---- stage X^T [k][node]: each thread does 16 k-values of one node ----
        {
            const int gn = base + sn;
            if (gn < NNODES) {
                const float4* xr = (const float4*)(X + (size_t)gn * IN_C + skq * 16);
                #pragma unroll
                for (int f = 0; f < 4; f++) {
                    float4 v = xr[f];
                    int k = skq * 16 + f * 4;
                    sXT[(k + 0) * XT_STR + sn] = v.x;
                    sXT[(k + 1) * XT_STR + sn] = v.y;
                    sXT[(k + 2) * XT_STR + sn] = v.z;
                    sXT[(k + 3) * XT_STR + sn] = v.w;
                }
            } else {
                #pragma unroll
                for (int f = 0; f < 4; f++) {
                    int k = skq * 16 + f * 4;
                    sXT[(k + 0) * XT_STR + sn] = 0.f;
                    sXT[(k + 1) * XT_STR + sn] = 0.f;
                    sXT[(k + 2) * XT_STR + sn] = 0.f;
                    sXT[(k + 3) * XT_STR + sn] = 0.f;
                }
            }
        }
        __syncthreads();

        // ---- Phase 1: 4 cols x 8 nodes per thread ----
        {
            float4 bias = ((const float4*)sb1)[c4a];
            float acc0[8], acc1[8], acc2[8], acc3[8];
            #pragma unroll
            for (int n = 0; n < 8; n++) {
                acc0[n] = bias.x; acc1[n] = bias.y;
                acc2[n] = bias.z; acc3[n] = bias.w;
            }

            #pragma unroll 8
            for (int k = 0; k < IN_C; k++) {
                float4 w  = *(const float4*)&sW1[k * HID + c4a * 4];
                const float* xr = &sXT[k * XT_STR + no * 8];
                float4 x0 = *(const float4*)(xr);
                float4 x1 = *(const float4*)(xr + 4);
                float xv[8] = {x0.x,x0.y,x0.z,x0.w, x1.x,x1.y,x1.z,x1.w};
                #pragma unroll
                for (int n = 0; n < 8; n++) {
                    acc0[n] = fmaf(w.x, xv[n], acc0[n]);
                    acc1[n] = fmaf(w.y, xv[n], acc1[n]);
                    acc2[n] = fmaf(w.z, xv[n], acc2[n]);
                    acc3[n] = fmaf(w.w, xv[n], acc3[n]);
                }
            }

            // relu + store: row = phi(col) = c*32 + c4a  (compile-time c)
            #pragma unroll
            for (int m = 0; m < 2; m++) {
                float* d0 = &sHT[(0 * 32 + c4a) * HT_STR + no * 8 + m * 4];
                float* d1 = &sHT[(1 * 32 + c4a) * HT_STR + no * 8 + m * 4];
                float* d2 = &sHT[(2 * 32 + c4a) * HT_STR + no * 8 + m * 4];
                float* d3 = &sHT[(3 * 32 + c4a) * HT_STR + no * 8 + m * 4];
                *(float4*)d0 = make_float4(fmaxf(acc0[m*4+0],0.f), fmaxf(acc0[m*4+1],0.f),
                                           fmaxf(acc0[m*4+2],0.f), fmaxf(acc0[m*4+3],0.f));
                *(float4*)d1 = make_float4(fmaxf(acc1[m*4+0],0.f), fmaxf(acc1[m*4+1],0.f),
                                           fmaxf(acc1[m*4+2],0.f), fmaxf(acc1[m*4+3],0.f));
                *(float4*)d2 = make_float4(fmaxf(acc2[m*4+0],0.f), fmaxf(acc2[m*4+1],0.f),
                                           fmaxf(acc2[m*4+2],0.f), fmaxf(acc2[m*4+3],0.f));
                *(float4*)d3 = make_float4(fmaxf(acc3[m*4+0],0.f), fmaxf(acc3[m*4+1],0.f),
                                           fmaxf(acc3[m*4+2],0.f), fmaxf(acc3[m*4+3],0.f));
            }
        }
        __syncthreads();

        // ---- Phase 2: 4 cols x 4 nodes per thread, iterate phys rows ----
        {
            float a0[4], a1[4], a2r[4], a3[4];
            #pragma unroll
            for (int n = 0; n < 4; n++) { a0[n]=0.f; a1[n]=0.f; a2r[n]=0.f; a3[n]=0.f; }

            #pragma unroll 8
            for (int r = 0; r < HID; r++) {
                float4 w  = *(const float4*)&sW2s[r * OUT_C + cq * 4];
                float4 x0 = *(const float4*)&sHT[r * HT_STR + ng * 4];
                float xv[4] = {x0.x, x0.y, x0.z, x0.w};
                #pragma unroll
                for (int n = 0; n < 4; n++) {
                    a0[n]  = fmaf(w.x, xv[n], a0[n]);
                    a1[n]  = fmaf(w.y, xv[n], a1[n]);
                    a2r[n] = fmaf(w.z, xv[n], a2r[n]);
                    a3[n]  = fmaf(w.w, xv[n], a3[n]);
                }
            }

            #pragma unroll
            for (int n = 0; n < 4; n++) {
                int gn = base + ng * 4 + n;
                if (gn < NNODES) {
                    *(float4*)&g_h2[(size_t)gn * OUT_C + cq * 4] =
                        make_float4(a0[n], a1[n], a2r[n], a3[n]);
                }
            }
        }
        __syncthreads();
    }
}

// ---------------------------------------------------------------------------
// Pull aggregation: one warp per dst node, lane owns a float2 column chunk.
// ---------------------------------------------------------------------------
__global__ __launch_bounds__(256) void k_pull(
    const float* __restrict__ b2, float* __restrict__ out)
{
    const int warp = (blockIdx.x * blockDim.x + threadIdx.x) >> 5;
    const int lane = threadIdx.x & 31;
    if (warp >= NNODES) return;
    const int n = warp;

    const float2* __restrict__ tab = (const float2*)g_h2;
    const float din = g_dinv[n];

    float2 self = tab[(size_t)n * (OUT_C / 2) + lane];
    float2 acc;
    acc.x = din * self.x;
    acc.y = din * self.y;

    const int deg = g_degi[n];
    const int end = g_off[n];
    const int beg = end - deg;

    int i = beg;
    for (; i + 1 < end; i += 2) {
        const int s0 = __ldg(&g_esrc[i]);
        const int s1 = __ldg(&g_esrc[i + 1]);
        const float d0 = g_dinv[s0];
        const float d1 = g_dinv[s1];
        float2 v0 = tab[(size_t)s0 * (OUT_C / 2) + lane];
        float2 v1 = tab[(size_t)s1 * (OUT_C / 2) + lane];
        acc.x = fmaf(d0, v0.x, acc.x);
        acc.y = fmaf(d0, v0.y, acc.y);
        acc.x = fmaf(d1, v1.x, acc.x);
        acc.y = fmaf(d1, v1.y, acc.y);
    }
    if (i < end) {
        const int s = __ldg(&g_esrc[i]);
        const float ds = g_dinv[s];
        float2 v = tab[(size_t)s * (OUT_C / 2) + lane];
        acc.x = fmaf(ds, v.x, acc.x);
        acc.y = fmaf(ds, v.y, acc.y);
    }

    const float2 bb = ((const float2*)b2)[lane];
    float2 o;
    o.x = fmaf(din, acc.x, bb.x);
    o.y = fmaf(din, acc.y, bb.y);
    ((float2*)out)[(size_t)n * (OUT_C / 2) + lane] = o;
}

// ---------------------------------------------------------------------------
extern "C" void kernel_launch(void* const* d_in, const int* in_sizes, int n_in,
                              void* d_out, int out_size)
{
    const float* X   = (const float*)d_in[0];
    const int*   ei  = (const int*)d_in[1];
    const float* W1  = (const float*)d_in[2];
    const float* b1  = (const float*)d_in[3];
    const float* W2  = (const float*)d_in[4];
    const float* b2  = (const float*)d_in[5];
    float*       out = (float*)d_out;

    const int smem_bytes =
        (IN_C*HID + HID*OUT_C + HID + IN_C*XT_STR + HID*HT_STR) * 4;  // ~164 KB

    static cudaStream_t s1;
    static cudaEvent_t evRoot, evMlp;
    static void *p_degi, *p_state;
    static int init_done = 0;
    if (!init_done) {
        cudaFuncSetAttribute(k_mlp, cudaFuncAttributeMaxDynamicSharedMemorySize, smem_bytes);
        cudaStreamCreateWithFlags(&s1, cudaStreamNonBlocking);
        cudaEventCreateWithFlags(&evRoot, cudaEventDisableTiming);
        cudaEventCreateWithFlags(&evMlp, cudaEventDisableTiming);
        cudaGetSymbolAddress(&p_degi, g_degi);
        cudaGetSymbolAddress(&p_state, g_scanstate);
        init_done = 1;
    }

    cudaEventRecord(evRoot, 0);

    // Critical chain on the capture (legacy) stream.
    cudaMemsetAsync(p_degi, 0, NNODES * sizeof(int), 0);
    cudaMemsetAsync(p_state, 0, SCAN_NB * sizeof(unsigned long long), 0);
    k_deg_count<<<(NEDGES + 255) / 256, 256>>>(ei);
    k_scan     <<<SCAN_NB, SCAN_BLK>>>();
    k_scatter  <<<(NEDGES + 255) / 256, 256>>>(ei);

    // Fork: MLP depends only on the root.
    cudaStreamWaitEvent(s1, evRoot, 0);
    k_mlp<<<148, MLP_THREADS, smem_bytes, s1>>>(X, W1, b1, W2);
    cudaEventRecord(evMlp, s1);

    // Join, then pull.
    cudaStreamWaitEvent(0, evMlp, 0);
    k_pull     <<<(NNODES * 32 + 255) / 256, 256>>>(b2, out);
}